// round 3
// baseline (speedup 1.0000x reference)
#include <cuda_runtime.h>

// Problem shape (reference): B=8, C=21, H=W=512.
#define NUM_C  21
#define HW     (512 * 512)          // elements per (b,c) slab
#define HW4    (HW / 4)             // float4s per slab
#define BPS    16                   // blocks per slab
#define THREADS 256
#define CHUNK4 (HW4 / BPS)          // float4s per block
#define STRIDE 64                   // padded row stride (63 counters used)
#define MAX_ROWS 256                // supports up to B=16

// Partials: row = b*BPS + sub, col = c*3 + {inter,pred,target}.
// Every slot is overwritten each launch -> no zeroing needed.
__device__ unsigned int g_part[MAX_ROWS * STRIDE];
__device__ unsigned int g_done;     // static-init 0; last block resets to 0

__global__ __launch_bounds__(THREADS) void iou_kernel(
    const float* __restrict__ preds,
    const float* __restrict__ target,
    float* __restrict__ out,
    int rows)                        // = B * BPS
{
    const int tid  = threadIdx.x;
    const int slab = blockIdx.x / BPS;     // b*NUM_C + c
    const int sub  = blockIdx.x % BPS;
    const int c    = slab % NUM_C;
    const int b    = slab / NUM_C;

    const float4* __restrict__ p4 =
        reinterpret_cast<const float4*>(preds)  + (long long)slab * HW4;
    const float4* __restrict__ t4 =
        reinterpret_cast<const float4*>(target) + (long long)slab * HW4;

    const int start = sub * CHUNK4;

    unsigned int cp = 0, ct = 0, ci = 0;

    #pragma unroll 8
    for (int j = start + tid; j < start + CHUNK4; j += THREADS) {
        float4 p = p4[j];
        float4 t = t4[j];
        unsigned int px = p.x >= 0.5f, py = p.y >= 0.5f,
                     pz = p.z >= 0.5f, pw = p.w >= 0.5f;
        unsigned int tx = t.x == 1.0f, ty = t.y == 1.0f,
                     tz = t.z == 1.0f, tw = t.w == 1.0f;
        cp += px + py + pz + pw;
        ct += tx + ty + tz + tw;
        ci += (px & tx) + (py & ty) + (pz & tz) + (pw & tw);
    }

    // Warp reduce
    #pragma unroll
    for (int off = 16; off > 0; off >>= 1) {
        cp += __shfl_down_sync(0xFFFFFFFFu, cp, off);
        ct += __shfl_down_sync(0xFFFFFFFFu, ct, off);
        ci += __shfl_down_sync(0xFFFFFFFFu, ci, off);
    }

    // Block reduce via shared atomics
    __shared__ unsigned int s_cp, s_ct, s_ci;
    __shared__ unsigned int s_last;
    if (tid == 0) { s_cp = 0u; s_ct = 0u; s_ci = 0u; }
    __syncthreads();
    if ((tid & 31) == 0) {
        atomicAdd(&s_cp, cp);
        atomicAdd(&s_ct, ct);
        atomicAdd(&s_ci, ci);
    }
    __syncthreads();

    // Publish partials; elect last block
    if (tid == 0) {
        const int row = b * BPS + sub;
        unsigned int* dst = &g_part[row * STRIDE + c * 3];
        dst[0] = s_ci;
        dst[1] = s_cp;
        dst[2] = s_ct;
        __threadfence();
        unsigned int old = atomicAdd(&g_done, 1u);
        s_last = (old == gridDim.x - 1) ? 1u : 0u;
    }
    __syncthreads();
    if (!s_last) return;

    // ---- last block: reduce partials and write output ----
    __shared__ unsigned int s_sum[63];
    if (tid < 63) s_sum[tid] = 0u;
    __syncthreads();

    if (tid < 252) {
        const int k   = tid % 63;         // counter id: c*3 + kind
        const int q   = tid / 63;         // quarter 0..3
        const int per = rows / 4;
        unsigned int acc = 0;
        #pragma unroll 8
        for (int j = q * per; j < (q + 1) * per; ++j)
            acc += __ldcg(&g_part[j * STRIDE + k]);   // bypass L1 (cross-SM data)
        atomicAdd(&s_sum[k], acc);
    }
    __syncthreads();

    if (tid < NUM_C) {
        float inter = (float)s_sum[tid * 3 + 0];
        float psum  = (float)s_sum[tid * 3 + 1];
        float tsum  = (float)s_sum[tid * 3 + 2];
        float uni   = psum + tsum - inter;
        out[tid] = (uni == 0.0f) ? __int_as_float(0x7FC00000)
                                 : inter / fmaxf(uni, 1.0f);
    }
    if (tid == 0) g_done = 0u;   // restore invariant for next (graph) launch
}

extern "C" void kernel_launch(void* const* d_in, const int* in_sizes, int n_in,
                              void* d_out, int out_size)
{
    const float* preds  = (const float*)d_in[0];
    const float* target = (const float*)d_in[1];
    float* out = (float*)d_out;

    const int slabs = in_sizes[0] / HW;    // B * NUM_C (168 for reference)
    const int rows  = (slabs / NUM_C) * BPS;

    iou_kernel<<<slabs * BPS, THREADS>>>(preds, target, out, rows);
}